// round 15
// baseline (speedup 1.0000x reference)
#include <cuda_runtime.h>
#include <cuda_fp16.h>
#include <mma.h>
#include <math.h>

using namespace nvcuda;

#define N_MAX   100000
#define E_MAX   3300000
#define IN_DIM  128
#define HID     32
#define TILE    64
#define FULL    0xffffffffu

// ---- scratch (no allocation allowed) ----
__device__ __align__(16) __half g_hA[(size_t)N_MAX * HID];   // fp16: dinv * (x@W1)
__device__ __align__(16) __half g_hB[(size_t)N_MAX * HID];   // fp16: dinv * (h@W2)
__device__ float g_dinv[N_MAX];
__device__ int   g_cnt[N_MAX];      // in-degree (no self loop)
__device__ int   g_base[N_MAX];     // bucket base
__device__ int   g_esrc[E_MAX];     // bucketed src ids
__device__ int   g_eoff[E_MAX];     // per-edge offset within its dst bucket
__device__ int   g_total;
__device__ float g_scores[N_MAX + 1];
__device__ float g_max_v;
__device__ float g_sum_v;

// ============ init ============
__global__ void k_init(const float* __restrict__ cash, int N) {
    int i = blockIdx.x * blockDim.x + threadIdx.x;
    if (i < N) g_cnt[i] = 0;
    if (i == 0) {
        g_total = 0;
        g_max_v = -INFINITY;
        g_sum_v = 0.0f;
        g_scores[0] = cash[0];
    }
}

// ============ count in-degree, record within-bucket offset (coalesced) ============
__global__ void k_count(const int* __restrict__ dst, int E) {
    int i = blockIdx.x * blockDim.x + threadIdx.x;
    if (i < E) g_eoff[i] = atomicAdd(&g_cnt[dst[i]], 1);
}

// ============ prep: dinv = rsqrt(deg), bucket bases via warp-scan ============
__global__ void k_prep(int N) {
    int i = blockIdx.x * blockDim.x + threadIdx.x;
    int lane = threadIdx.x & 31;
    int cnt = (i < N) ? g_cnt[i] : 0;
    if (i < N) g_dinv[i] = rsqrtf((float)(cnt + 1));   // +1 self-loop

    int c = cnt;
    #pragma unroll
    for (int o = 1; o < 32; o <<= 1) {
        int t = __shfl_up_sync(FULL, c, o);
        if (lane >= o) c += t;
    }
    int warptot = __shfl_sync(FULL, c, 31);
    int excl = c - cnt;
    int wbase = 0;
    if (lane == 0) wbase = atomicAdd(&g_total, warptot);
    wbase = __shfl_sync(FULL, wbase, 0);
    if (i < N) g_base[i] = wbase + excl;
}

// ============ merged: odd blocks fill buckets, even blocks do tensor-core GEMM1 ============
// gemm role: hA = fp16(dinv * (x @ W1)) via wmma m16n16k16, fp32 accumulate.
// N is divisible by 16 (100000/16=6250) so all row tiles are full.
__global__ __launch_bounds__(256) void k_fill_gemm1(
    const int* __restrict__ src, const int* __restrict__ dst, int E,
    const float* __restrict__ x, const float* __restrict__ W1, int N)
{
    __shared__ __align__(16) __half sxh[TILE * IN_DIM];   // 16 KB fp16 x tile
    __shared__ __align__(16) __half sWh[IN_DIM * HID];    //  8 KB fp16 W1
    __shared__ __align__(16) float  sOut[TILE * HID];     //  8 KB fp32 result
    int half_g = gridDim.x >> 1;
    int role_b = blockIdx.x >> 1;

    if (blockIdx.x & 1) {
        // ---- fill role (atomic-free scatter) ----
        for (int i = role_b * blockDim.x + threadIdx.x; i < E;
             i += half_g * blockDim.x) {
            int d = dst[i];
            g_esrc[g_base[d] + g_eoff[i]] = src[i];
        }
        return;
    }

    // ---- gemm role ----
    for (int i = threadIdx.x; i < IN_DIM * HID; i += blockDim.x)
        sWh[i] = __float2half(W1[i]);
    int warp = threadIdx.x >> 5;
    int rt = warp >> 1;          // row tile 0..3 (16 rows each)
    int ct = warp & 1;           // col tile 0..1 (16 cols each)

    for (int tile = role_b * TILE; tile < N; tile += half_g * TILE) {
        __syncthreads();                        // protect sxh/sOut reuse
        int rows = min(TILE, N - tile);         // 64 or 32; multiple of 16
        // stage x tile as fp16 (coalesced float4 reads)
        for (int i = threadIdx.x; i < rows * (IN_DIM / 4); i += blockDim.x) {
            int r = i >> 5, c = i & 31;
            float4 v = ((const float4*)(x + (size_t)(tile + r) * IN_DIM))[c];
            __half2* dh = (__half2*)(sxh + r * IN_DIM + c * 4);
            dh[0] = __floats2half2_rn(v.x, v.y);
            dh[1] = __floats2half2_rn(v.z, v.w);
        }
        __syncthreads();

        if (rt * 16 < rows) {
            wmma::fragment<wmma::accumulator, 16, 16, 16, float> cfrag;
            wmma::fill_fragment(cfrag, 0.0f);
            #pragma unroll
            for (int k = 0; k < IN_DIM; k += 16) {
                wmma::fragment<wmma::matrix_a, 16, 16, 16, __half, wmma::row_major> afrag;
                wmma::fragment<wmma::matrix_b, 16, 16, 16, __half, wmma::row_major> bfrag;
                wmma::load_matrix_sync(afrag, sxh + rt * 16 * IN_DIM + k, IN_DIM);
                wmma::load_matrix_sync(bfrag, sWh + k * HID + ct * 16, HID);
                wmma::mma_sync(cfrag, afrag, bfrag, cfrag);
            }
            wmma::store_matrix_sync(sOut + rt * 16 * HID + ct * 16, cfrag, HID,
                                    wmma::mem_row_major);
        }
        __syncthreads();

        // scale by dinv, emit half2
        for (int i = threadIdx.x; i < rows * 16; i += blockDim.x) {
            int r = i >> 4, cp = i & 15;
            int n = tile + r;
            float dd = g_dinv[n];
            float vx = sOut[r * HID + cp * 2];
            float vy = sOut[r * HID + cp * 2 + 1];
            ((__half2*)g_hA)[(size_t)n * 16 + cp] = __floats2half2_rn(dd * vx, dd * vy);
        }
    }
}

// ============ fp16 gather core ============
// Warp per dst row. lanes 0-15 accumulate even-slot edges, lanes 16-31 odd-slot.
// Each lane loads one half2 = channel pair (lane&15). fp32 accumulation.
__device__ __forceinline__ float gather_row_h(const __half* __restrict__ fromh,
                                              int d, int lane, int* __restrict__ sIdx) {
    const __half2* from = (const __half2*)fromh;
    int base = g_base[d], cnt = g_cnt[d];
    int cp = lane & 15;          // channel-pair index
    int hid = lane >> 4;         // 0: even edges, 1: odd edges
    float ax = 0.f, ay = 0.f;
    if (hid == 0) {
        float2 t = __half22float2(from[(size_t)d * 16 + cp]);
        ax = t.x; ay = t.y;
    }
    for (int j0 = 0; j0 < cnt; j0 += 32) {
        int jn = min(32, cnt - j0);
        if (lane < jn) sIdx[lane] = g_esrc[base + j0 + lane];
        __syncwarp();
        int j = 0;
        for (; j + 8 <= jn; j += 8) {
            int s0 = sIdx[j + hid];
            int s1 = sIdx[j + 2 + hid];
            int s2 = sIdx[j + 4 + hid];
            int s3 = sIdx[j + 6 + hid];
            float2 v0 = __half22float2(from[(size_t)s0 * 16 + cp]);
            float2 v1 = __half22float2(from[(size_t)s1 * 16 + cp]);
            float2 v2 = __half22float2(from[(size_t)s2 * 16 + cp]);
            float2 v3 = __half22float2(from[(size_t)s3 * 16 + cp]);
            ax += (v0.x + v1.x) + (v2.x + v3.x);
            ay += (v0.y + v1.y) + (v2.y + v3.y);
        }
        for (; j + 2 <= jn; j += 2) {
            int s = sIdx[j + hid];
            float2 v = __half22float2(from[(size_t)s * 16 + cp]);
            ax += v.x; ay += v.y;
        }
        if (j < jn && hid == 0) {          // odd leftover edge
            int s = sIdx[j];
            float2 v = __half22float2(from[(size_t)s * 16 + cp]);
            ax += v.x; ay += v.y;
        }
        __syncwarp();
    }
    ax += __shfl_down_sync(FULL, ax, 16);
    ay += __shfl_down_sync(FULL, ay, 16);
    float hx = __shfl_sync(FULL, ax, lane >> 1);
    float hy = __shfl_sync(FULL, ay, lane >> 1);
    return (lane & 1) ? hy : hx;
}

// ============ gather1 + fused gemm2: hB = fp16(dinv * (relu(dinv*sum + b1) @ W2)) ============
__global__ void k_gather1(const float* __restrict__ W2, const float* __restrict__ b1, int N) {
    __shared__ float sW[HID * HID];
    __shared__ __align__(16) int sIdxAll[8][32];
    for (int i = threadIdx.x; i < HID * HID; i += blockDim.x) sW[i] = W2[i];
    __syncthreads();

    int lane = threadIdx.x & 31;
    int warp = threadIdx.x >> 5;
    int* sIdx = sIdxAll[warp];
    int gwarp = blockIdx.x * (blockDim.x >> 5) + warp;
    int nw = gridDim.x * (blockDim.x >> 5);
    float bb = b1[lane];

    for (int d = gwarp; d < N; d += nw) {
        float t = gather_row_h(g_hA, d, lane, sIdx);
        float dd = g_dinv[d];
        float h = fmaxf(fmaf(dd, t, bb), 0.0f);
        float o = 0.0f;
        #pragma unroll
        for (int k = 0; k < HID; k++) {
            float hk = __shfl_sync(FULL, h, k);
            o = fmaf(hk, sW[k * HID + lane], o);
        }
        g_hB[(size_t)d * HID + lane] = __float2half(dd * o);
    }
}

// ============ gather2 + fused head: scores[d+1] = relu(dinv*sum+b2).Wh + bh ============
__global__ void k_gather2(const float* __restrict__ Wh, const float* __restrict__ b2,
                          const float* __restrict__ bh, int N) {
    __shared__ __align__(16) int sIdxAll[8][32];
    int lane = threadIdx.x & 31;
    int warp = threadIdx.x >> 5;
    int* sIdx = sIdxAll[warp];
    int gwarp = blockIdx.x * (blockDim.x >> 5) + warp;
    int nw = gridDim.x * (blockDim.x >> 5);
    float bb = b2[lane], wh = Wh[lane], bhv = bh[0];

    for (int d = gwarp; d < N; d += nw) {
        float t = gather_row_h(g_hB, d, lane, sIdx);
        float dd = g_dinv[d];
        float v = fmaxf(fmaf(dd, t, bb), 0.0f) * wh;
        #pragma unroll
        for (int o = 16; o > 0; o >>= 1) v += __shfl_xor_sync(FULL, v, o);
        if (lane == 0) g_scores[d + 1] = v + bhv;
    }
}

// ============ softmax ============
__device__ __forceinline__ void atomicMaxF(float* addr, float v) {
    if (v >= 0.0f) atomicMax((int*)addr, __float_as_int(v));
    else           atomicMin((unsigned int*)addr, __float_as_uint(v));
}

__global__ void k_max(int M) {
    float m = -INFINITY;
    for (int i = blockIdx.x * blockDim.x + threadIdx.x; i < M; i += gridDim.x * blockDim.x)
        m = fmaxf(m, g_scores[i]);
    #pragma unroll
    for (int o = 16; o > 0; o >>= 1) m = fmaxf(m, __shfl_xor_sync(FULL, m, o));
    __shared__ float sm[32];
    if ((threadIdx.x & 31) == 0) sm[threadIdx.x >> 5] = m;
    __syncthreads();
    if (threadIdx.x < 32) {
        float v = (threadIdx.x < (blockDim.x >> 5)) ? sm[threadIdx.x] : -INFINITY;
        #pragma unroll
        for (int o = 16; o > 0; o >>= 1) v = fmaxf(v, __shfl_xor_sync(FULL, v, o));
        if (threadIdx.x == 0) atomicMaxF(&g_max_v, v);
    }
}

__global__ void k_sumexp(int M) {
    float mx = g_max_v;
    float s = 0.0f;
    for (int i = blockIdx.x * blockDim.x + threadIdx.x; i < M; i += gridDim.x * blockDim.x)
        s += expf(g_scores[i] - mx);
    #pragma unroll
    for (int o = 16; o > 0; o >>= 1) s += __shfl_xor_sync(FULL, s, o);
    __shared__ float sm[32];
    if ((threadIdx.x & 31) == 0) sm[threadIdx.x >> 5] = s;
    __syncthreads();
    if (threadIdx.x < 32) {
        float v = (threadIdx.x < (blockDim.x >> 5)) ? sm[threadIdx.x] : 0.0f;
        #pragma unroll
        for (int o = 16; o > 0; o >>= 1) v += __shfl_xor_sync(FULL, v, o);
        if (threadIdx.x == 0) atomicAdd(&g_sum_v, v);
    }
}

__global__ void k_norm(float* __restrict__ out, int M) {
    float mx = g_max_v;
    float inv = 1.0f / g_sum_v;
    for (int i = blockIdx.x * blockDim.x + threadIdx.x; i < M; i += gridDim.x * blockDim.x)
        out[i] = expf(g_scores[i] - mx) * inv;
}

// ============ launch ============
extern "C" void kernel_launch(void* const* d_in, const int* in_sizes, int n_in,
                              void* d_out, int out_size) {
    const float* x    = (const float*)d_in[0];
    const int*   ei   = (const int*)d_in[1];     // int32 (JAX x64 disabled)
    const float* W1   = (const float*)d_in[2];
    const float* b1   = (const float*)d_in[3];
    const float* W2   = (const float*)d_in[4];
    const float* b2   = (const float*)d_in[5];
    const float* Wh   = (const float*)d_in[6];
    const float* bh   = (const float*)d_in[7];
    const float* cash = (const float*)d_in[8];
    float* out = (float*)d_out;

    int N = in_sizes[0] / IN_DIM;
    int E = in_sizes[1] / 2;
    const int* src = ei;
    const int* dst = ei + E;
    int M = N + 1;

    // CSR bucket build
    k_init<<<(N + 255) / 256, 256>>>(cash, N);
    k_count<<<(E + 255) / 256, 256>>>(dst, E);
    k_prep<<<(N + 255) / 256, 256>>>(N);

    // fill (odd blocks) co-running with tensor-core gemm1 (even blocks)
    int gemm_blocks = (N + TILE - 1) / TILE;
    k_fill_gemm1<<<2 * gemm_blocks, 256>>>(src, dst, E, x, W1, N);

    // layer 1 propagate + fused gemm2
    k_gather1<<<(N + 7) / 8, 256>>>(W2, b1, N);
    // layer 2 propagate + fused head
    k_gather2<<<(N + 7) / 8, 256>>>(Wh, b2, bh, N);

    // softmax
    k_max<<<256, 256>>>(M);
    k_sumexp<<<256, 256>>>(M);
    k_norm<<<(M + 255) / 256, 256>>>(out, M);
}

// round 16
// speedup vs baseline: 1.0190x; 1.0190x over previous
#include <cuda_runtime.h>
#include <cuda_fp16.h>
#include <mma.h>
#include <math.h>

using namespace nvcuda;

#define N_MAX   100000
#define E_MAX   3300000
#define IN_DIM  128
#define HID     32
#define TILE    64
#define FULL    0xffffffffu

// ---- scratch (no allocation allowed) ----
__device__ __align__(16) __half g_hA[(size_t)N_MAX * HID];   // fp16: dinv * (x@W1)
__device__ __align__(16) __half g_hB[(size_t)N_MAX * HID];   // fp16: dinv * (h@W2)
__device__ float g_dinv[N_MAX];
__device__ int   g_cnt[N_MAX];      // in-degree (no self loop)
__device__ int   g_base[N_MAX];     // bucket base
__device__ int   g_esrc[E_MAX];     // bucketed src ids
__device__ int   g_eoff[E_MAX];     // per-edge offset within its dst bucket
__device__ int   g_total;
__device__ float g_scores[N_MAX + 1];
__device__ float g_max_v;
__device__ float g_sum_v;

// ============ init ============
__global__ void k_init(const float* __restrict__ cash, int N) {
    int i = blockIdx.x * blockDim.x + threadIdx.x;
    if (i < N) g_cnt[i] = 0;
    if (i == 0) {
        g_total = 0;
        g_max_v = -INFINITY;
        g_sum_v = 0.0f;
        g_scores[0] = cash[0];
    }
}

// ============ count in-degree, record within-bucket offset (coalesced) ============
__global__ void k_count(const int* __restrict__ dst, int E) {
    int i = blockIdx.x * blockDim.x + threadIdx.x;
    if (i < E) g_eoff[i] = atomicAdd(&g_cnt[dst[i]], 1);
}

// ============ prep: dinv = rsqrt(deg), bucket bases via warp-scan ============
__global__ void k_prep(int N) {
    int i = blockIdx.x * blockDim.x + threadIdx.x;
    int lane = threadIdx.x & 31;
    int cnt = (i < N) ? g_cnt[i] : 0;
    if (i < N) g_dinv[i] = rsqrtf((float)(cnt + 1));   // +1 self-loop

    int c = cnt;
    #pragma unroll
    for (int o = 1; o < 32; o <<= 1) {
        int t = __shfl_up_sync(FULL, c, o);
        if (lane >= o) c += t;
    }
    int warptot = __shfl_sync(FULL, c, 31);
    int excl = c - cnt;
    int wbase = 0;
    if (lane == 0) wbase = atomicAdd(&g_total, warptot);
    wbase = __shfl_sync(FULL, wbase, 0);
    if (i < N) g_base[i] = wbase + excl;
}

// ============ fill buckets: atomic-free scatter of src ids ============
__global__ void k_fill(const int* __restrict__ src, const int* __restrict__ dst, int E) {
    int i = blockIdx.x * blockDim.x + threadIdx.x;
    if (i < E) {
        int d = dst[i];
        g_esrc[g_base[d] + g_eoff[i]] = src[i];
    }
}

// ============ GEMM1 (tensor cores, standalone): hA = fp16(dinv * (x @ W1)) ============
// wmma m16n16k16, fp32 accumulate. N divisible by 16 -> full tiles.
__global__ __launch_bounds__(256) void k_gemm1(
    const float* __restrict__ x, const float* __restrict__ W1, int N)
{
    __shared__ __align__(16) __half sxh[TILE * IN_DIM];   // 16 KB fp16 x tile
    __shared__ __align__(16) __half sWh[IN_DIM * HID];    //  8 KB fp16 W1
    __shared__ __align__(16) float  sOut[TILE * HID];     //  8 KB fp32 result

    for (int i = threadIdx.x; i < IN_DIM * HID; i += blockDim.x)
        sWh[i] = __float2half(W1[i]);
    int warp = threadIdx.x >> 5;
    int rt = warp >> 1;          // row tile 0..3
    int ct = warp & 1;           // col tile 0..1

    for (int tile = blockIdx.x * TILE; tile < N; tile += gridDim.x * TILE) {
        __syncthreads();                        // protect sxh/sOut reuse
        int rows = min(TILE, N - tile);         // multiple of 16
        for (int i = threadIdx.x; i < rows * (IN_DIM / 4); i += blockDim.x) {
            int r = i >> 5, c = i & 31;
            float4 v = __ldg((const float4*)(x + (size_t)(tile + r) * IN_DIM) + c);
            __half2* dh = (__half2*)(sxh + r * IN_DIM + c * 4);
            dh[0] = __floats2half2_rn(v.x, v.y);
            dh[1] = __floats2half2_rn(v.z, v.w);
        }
        __syncthreads();

        if (rt * 16 < rows) {
            wmma::fragment<wmma::accumulator, 16, 16, 16, float> cfrag;
            wmma::fill_fragment(cfrag, 0.0f);
            #pragma unroll
            for (int k = 0; k < IN_DIM; k += 16) {
                wmma::fragment<wmma::matrix_a, 16, 16, 16, __half, wmma::row_major> afrag;
                wmma::fragment<wmma::matrix_b, 16, 16, 16, __half, wmma::row_major> bfrag;
                wmma::load_matrix_sync(afrag, sxh + rt * 16 * IN_DIM + k, IN_DIM);
                wmma::load_matrix_sync(bfrag, sWh + k * HID + ct * 16, HID);
                wmma::mma_sync(cfrag, afrag, bfrag, cfrag);
            }
            wmma::store_matrix_sync(sOut + rt * 16 * HID + ct * 16, cfrag, HID,
                                    wmma::mem_row_major);
        }
        __syncthreads();

        for (int i = threadIdx.x; i < rows * 16; i += blockDim.x) {
            int r = i >> 4, cp = i & 15;
            int n = tile + r;
            float dd = g_dinv[n];
            float2 v = *(const float2*)(sOut + r * HID + cp * 2);
            ((__half2*)g_hA)[(size_t)n * 16 + cp] = __floats2half2_rn(dd * v.x, dd * v.y);
        }
    }
}

// ============ fp16 gather core ============
// Warp per dst row. lanes 0-15 accumulate even-slot edges, lanes 16-31 odd-slot.
// Each lane loads one half2 = channel pair (lane&15). fp32 accumulation.
__device__ __forceinline__ float gather_row_h(const __half* __restrict__ fromh,
                                              int d, int lane, int* __restrict__ sIdx) {
    const __half2* from = (const __half2*)fromh;
    int base = g_base[d], cnt = g_cnt[d];
    int cp = lane & 15;          // channel-pair index
    int hid = lane >> 4;         // 0: even edges, 1: odd edges
    float ax = 0.f, ay = 0.f;
    if (hid == 0) {
        float2 t = __half22float2(from[(size_t)d * 16 + cp]);
        ax = t.x; ay = t.y;
    }
    for (int j0 = 0; j0 < cnt; j0 += 32) {
        int jn = min(32, cnt - j0);
        if (lane < jn) sIdx[lane] = g_esrc[base + j0 + lane];
        __syncwarp();
        int j = 0;
        for (; j + 8 <= jn; j += 8) {
            int s0 = sIdx[j + hid];
            int s1 = sIdx[j + 2 + hid];
            int s2 = sIdx[j + 4 + hid];
            int s3 = sIdx[j + 6 + hid];
            float2 v0 = __half22float2(from[(size_t)s0 * 16 + cp]);
            float2 v1 = __half22float2(from[(size_t)s1 * 16 + cp]);
            float2 v2 = __half22float2(from[(size_t)s2 * 16 + cp]);
            float2 v3 = __half22float2(from[(size_t)s3 * 16 + cp]);
            ax += (v0.x + v1.x) + (v2.x + v3.x);
            ay += (v0.y + v1.y) + (v2.y + v3.y);
        }
        for (; j + 2 <= jn; j += 2) {
            int s = sIdx[j + hid];
            float2 v = __half22float2(from[(size_t)s * 16 + cp]);
            ax += v.x; ay += v.y;
        }
        if (j < jn && hid == 0) {          // odd leftover edge
            int s = sIdx[j];
            float2 v = __half22float2(from[(size_t)s * 16 + cp]);
            ax += v.x; ay += v.y;
        }
        __syncwarp();
    }
    ax += __shfl_down_sync(FULL, ax, 16);
    ay += __shfl_down_sync(FULL, ay, 16);
    float hx = __shfl_sync(FULL, ax, lane >> 1);
    float hy = __shfl_sync(FULL, ay, lane >> 1);
    return (lane & 1) ? hy : hx;
}

// ============ gather1 + fused gemm2: hB = fp16(dinv * (relu(dinv*sum + b1) @ W2)) ============
__global__ void k_gather1(const float* __restrict__ W2, const float* __restrict__ b1, int N) {
    __shared__ float sW[HID * HID];
    __shared__ __align__(16) int sIdxAll[8][32];
    for (int i = threadIdx.x; i < HID * HID; i += blockDim.x) sW[i] = W2[i];
    __syncthreads();

    int lane = threadIdx.x & 31;
    int warp = threadIdx.x >> 5;
    int* sIdx = sIdxAll[warp];
    int gwarp = blockIdx.x * (blockDim.x >> 5) + warp;
    int nw = gridDim.x * (blockDim.x >> 5);
    float bb = b1[lane];

    for (int d = gwarp; d < N; d += nw) {
        float t = gather_row_h(g_hA, d, lane, sIdx);
        float dd = g_dinv[d];
        float h = fmaxf(fmaf(dd, t, bb), 0.0f);
        float o = 0.0f;
        #pragma unroll
        for (int k = 0; k < HID; k++) {
            float hk = __shfl_sync(FULL, h, k);
            o = fmaf(hk, sW[k * HID + lane], o);
        }
        g_hB[(size_t)d * HID + lane] = __float2half(dd * o);
    }
}

// ============ gather2 + fused head: scores[d+1] = relu(dinv*sum+b2).Wh + bh ============
__global__ void k_gather2(const float* __restrict__ Wh, const float* __restrict__ b2,
                          const float* __restrict__ bh, int N) {
    __shared__ __align__(16) int sIdxAll[8][32];
    int lane = threadIdx.x & 31;
    int warp = threadIdx.x >> 5;
    int* sIdx = sIdxAll[warp];
    int gwarp = blockIdx.x * (blockDim.x >> 5) + warp;
    int nw = gridDim.x * (blockDim.x >> 5);
    float bb = b2[lane], wh = Wh[lane], bhv = bh[0];

    for (int d = gwarp; d < N; d += nw) {
        float t = gather_row_h(g_hB, d, lane, sIdx);
        float dd = g_dinv[d];
        float v = fmaxf(fmaf(dd, t, bb), 0.0f) * wh;
        #pragma unroll
        for (int o = 16; o > 0; o >>= 1) v += __shfl_xor_sync(FULL, v, o);
        if (lane == 0) g_scores[d + 1] = v + bhv;
    }
}

// ============ softmax ============
__device__ __forceinline__ void atomicMaxF(float* addr, float v) {
    if (v >= 0.0f) atomicMax((int*)addr, __float_as_int(v));
    else           atomicMin((unsigned int*)addr, __float_as_uint(v));
}

__global__ void k_max(int M) {
    float m = -INFINITY;
    for (int i = blockIdx.x * blockDim.x + threadIdx.x; i < M; i += gridDim.x * blockDim.x)
        m = fmaxf(m, g_scores[i]);
    #pragma unroll
    for (int o = 16; o > 0; o >>= 1) m = fmaxf(m, __shfl_xor_sync(FULL, m, o));
    __shared__ float sm[32];
    if ((threadIdx.x & 31) == 0) sm[threadIdx.x >> 5] = m;
    __syncthreads();
    if (threadIdx.x < 32) {
        float v = (threadIdx.x < (blockDim.x >> 5)) ? sm[threadIdx.x] : -INFINITY;
        #pragma unroll
        for (int o = 16; o > 0; o >>= 1) v = fmaxf(v, __shfl_xor_sync(FULL, v, o));
        if (threadIdx.x == 0) atomicMaxF(&g_max_v, v);
    }
}

__global__ void k_sumexp(int M) {
    float mx = g_max_v;
    float s = 0.0f;
    for (int i = blockIdx.x * blockDim.x + threadIdx.x; i < M; i += gridDim.x * blockDim.x)
        s += expf(g_scores[i] - mx);
    #pragma unroll
    for (int o = 16; o > 0; o >>= 1) s += __shfl_xor_sync(FULL, s, o);
    __shared__ float sm[32];
    if ((threadIdx.x & 31) == 0) sm[threadIdx.x >> 5] = s;
    __syncthreads();
    if (threadIdx.x < 32) {
        float v = (threadIdx.x < (blockDim.x >> 5)) ? sm[threadIdx.x] : 0.0f;
        #pragma unroll
        for (int o = 16; o > 0; o >>= 1) v += __shfl_xor_sync(FULL, v, o);
        if (threadIdx.x == 0) atomicAdd(&g_sum_v, v);
    }
}

__global__ void k_norm(float* __restrict__ out, int M) {
    float mx = g_max_v;
    float inv = 1.0f / g_sum_v;
    for (int i = blockIdx.x * blockDim.x + threadIdx.x; i < M; i += gridDim.x * blockDim.x)
        out[i] = expf(g_scores[i] - mx) * inv;
}

// ============ launch ============
extern "C" void kernel_launch(void* const* d_in, const int* in_sizes, int n_in,
                              void* d_out, int out_size) {
    const float* x    = (const float*)d_in[0];
    const int*   ei   = (const int*)d_in[1];     // int32 (JAX x64 disabled)
    const float* W1   = (const float*)d_in[2];
    const float* b1   = (const float*)d_in[3];
    const float* W2   = (const float*)d_in[4];
    const float* b2   = (const float*)d_in[5];
    const float* Wh   = (const float*)d_in[6];
    const float* bh   = (const float*)d_in[7];
    const float* cash = (const float*)d_in[8];
    float* out = (float*)d_out;

    int N = in_sizes[0] / IN_DIM;
    int E = in_sizes[1] / 2;
    const int* src = ei;
    const int* dst = ei + E;
    int M = N + 1;

    // CSR bucket build
    k_init<<<(N + 255) / 256, 256>>>(cash, N);
    k_count<<<(E + 255) / 256, 256>>>(dst, E);
    k_prep<<<(N + 255) / 256, 256>>>(N);
    k_fill<<<(E + 255) / 256, 256>>>(src, dst, E);

    // dense transform on tensor cores
    k_gemm1<<<(N + TILE - 1) / TILE, 256>>>(x, W1, N);

    // layer 1 propagate + fused gemm2
    k_gather1<<<(N + 7) / 8, 256>>>(W2, b1, N);
    // layer 2 propagate + fused head
    k_gather2<<<(N + 7) / 8, 256>>>(Wh, b2, bh, N);

    // softmax
    k_max<<<256, 256>>>(M);
    k_sumexp<<<256, 256>>>(M);
    k_norm<<<(M + 255) / 256, 256>>>(out, M);
}

// round 17
// speedup vs baseline: 1.0290x; 1.0099x over previous
#include <cuda_runtime.h>
#include <cuda_fp16.h>
#include <mma.h>
#include <math.h>

using namespace nvcuda;

#define N_MAX   100000
#define E_MAX   3300000
#define IN_DIM  128
#define HID     32
#define TILE    64
#define FULL    0xffffffffu

// ---- scratch (no allocation allowed) ----
__device__ __align__(16) __half g_hA[(size_t)N_MAX * HID];   // fp16: dinv * (x@W1)
__device__ __align__(16) __half g_hB[(size_t)N_MAX * HID];   // fp16: dinv * (h@W2)
__device__ float g_dinv[N_MAX];
__device__ int   g_cnt[N_MAX];      // in-degree; zero at call entry (tail-zeroed by k_norm)
__device__ int   g_base[N_MAX];     // bucket base
__device__ int   g_esrc[E_MAX];     // bucketed src ids
__device__ int   g_eoff[E_MAX];     // per-edge offset within its dst bucket
__device__ int   g_total;
__device__ float g_scores[N_MAX + 1];
__device__ float g_sum_v;

// ============ count (vectorized x4): in-degree + within-bucket offsets ============
__global__ void k_count4(const int* __restrict__ dst, int E) {
    int i = (blockIdx.x * blockDim.x + threadIdx.x) * 4;
    if (i == 0) g_total = 0;                 // consumed by k_prep this call
    if (i + 3 < E) {
        int4 d = *(const int4*)(dst + i);
        int4 o;
        o.x = atomicAdd(&g_cnt[d.x], 1);
        o.y = atomicAdd(&g_cnt[d.y], 1);
        o.z = atomicAdd(&g_cnt[d.z], 1);
        o.w = atomicAdd(&g_cnt[d.w], 1);
        *(int4*)(g_eoff + i) = o;
    } else {
        for (; i < E; i++) g_eoff[i] = atomicAdd(&g_cnt[dst[i]], 1);
    }
}

__global__ void k_count1(const int* __restrict__ dst, int E) {
    int i = blockIdx.x * blockDim.x + threadIdx.x;
    if (i == 0) g_total = 0;
    if (i < E) g_eoff[i] = atomicAdd(&g_cnt[dst[i]], 1);
}

// ============ prep: dinv = rsqrt(deg), bucket bases via warp-scan ============
__global__ void k_prep(int N) {
    int i = blockIdx.x * blockDim.x + threadIdx.x;
    int lane = threadIdx.x & 31;
    if (i == 0) g_sum_v = 0.0f;              // accumulated by k_gather2 this call
    int cnt = (i < N) ? g_cnt[i] : 0;
    if (i < N) g_dinv[i] = rsqrtf((float)(cnt + 1));   // +1 self-loop

    int c = cnt;
    #pragma unroll
    for (int o = 1; o < 32; o <<= 1) {
        int t = __shfl_up_sync(FULL, c, o);
        if (lane >= o) c += t;
    }
    int warptot = __shfl_sync(FULL, c, 31);
    int excl = c - cnt;
    int wbase = 0;
    if (lane == 0) wbase = atomicAdd(&g_total, warptot);
    wbase = __shfl_sync(FULL, wbase, 0);
    if (i < N) g_base[i] = wbase + excl;
}

// ============ fill (vectorized x4): atomic-free scatter of src ids ============
__global__ void k_fill4(const int* __restrict__ src, const int* __restrict__ dst, int E) {
    int i = (blockIdx.x * blockDim.x + threadIdx.x) * 4;
    if (i + 3 < E) {
        int4 s = *(const int4*)(src + i);
        int4 d = *(const int4*)(dst + i);
        int4 o = *(const int4*)(g_eoff + i);
        g_esrc[g_base[d.x] + o.x] = s.x;
        g_esrc[g_base[d.y] + o.y] = s.y;
        g_esrc[g_base[d.z] + o.z] = s.z;
        g_esrc[g_base[d.w] + o.w] = s.w;
    } else {
        for (; i < E; i++) g_esrc[g_base[dst[i]] + g_eoff[i]] = src[i];
    }
}

__global__ void k_fill1(const int* __restrict__ src, const int* __restrict__ dst, int E) {
    int i = blockIdx.x * blockDim.x + threadIdx.x;
    if (i < E) g_esrc[g_base[dst[i]] + g_eoff[i]] = src[i];
}

// ============ GEMM1 (tensor cores): hA = fp16(dinv * (x @ W1)) ============
__global__ __launch_bounds__(256) void k_gemm1(
    const float* __restrict__ x, const float* __restrict__ W1, int N)
{
    __shared__ __align__(16) __half sxh[TILE * IN_DIM];   // 16 KB
    __shared__ __align__(16) __half sWh[IN_DIM * HID];    //  8 KB
    __shared__ __align__(16) float  sOut[TILE * HID];     //  8 KB

    for (int i = threadIdx.x; i < IN_DIM * HID; i += blockDim.x)
        sWh[i] = __float2half(W1[i]);
    int warp = threadIdx.x >> 5;
    int rt = warp >> 1;          // row tile 0..3
    int ct = warp & 1;           // col tile 0..1

    for (int tile = blockIdx.x * TILE; tile < N; tile += gridDim.x * TILE) {
        __syncthreads();
        int rows = min(TILE, N - tile);         // multiple of 16
        for (int i = threadIdx.x; i < rows * (IN_DIM / 4); i += blockDim.x) {
            int r = i >> 5, c = i & 31;
            float4 v = __ldg((const float4*)(x + (size_t)(tile + r) * IN_DIM) + c);
            __half2* dh = (__half2*)(sxh + r * IN_DIM + c * 4);
            dh[0] = __floats2half2_rn(v.x, v.y);
            dh[1] = __floats2half2_rn(v.z, v.w);
        }
        __syncthreads();

        if (rt * 16 < rows) {
            wmma::fragment<wmma::accumulator, 16, 16, 16, float> cfrag;
            wmma::fill_fragment(cfrag, 0.0f);
            #pragma unroll
            for (int k = 0; k < IN_DIM; k += 16) {
                wmma::fragment<wmma::matrix_a, 16, 16, 16, __half, wmma::row_major> afrag;
                wmma::fragment<wmma::matrix_b, 16, 16, 16, __half, wmma::row_major> bfrag;
                wmma::load_matrix_sync(afrag, sxh + rt * 16 * IN_DIM + k, IN_DIM);
                wmma::load_matrix_sync(bfrag, sWh + k * HID + ct * 16, HID);
                wmma::mma_sync(cfrag, afrag, bfrag, cfrag);
            }
            wmma::store_matrix_sync(sOut + rt * 16 * HID + ct * 16, cfrag, HID,
                                    wmma::mem_row_major);
        }
        __syncthreads();

        for (int i = threadIdx.x; i < rows * 16; i += blockDim.x) {
            int r = i >> 4, cp = i & 15;
            int n = tile + r;
            float dd = g_dinv[n];
            float2 v = *(const float2*)(sOut + r * HID + cp * 2);
            ((__half2*)g_hA)[(size_t)n * 16 + cp] = __floats2half2_rn(dd * v.x, dd * v.y);
        }
    }
}

// ============ fp16 gather core ============
__device__ __forceinline__ float gather_row_h(const __half* __restrict__ fromh,
                                              int d, int lane, int* __restrict__ sIdx) {
    const __half2* from = (const __half2*)fromh;
    int base = g_base[d], cnt = g_cnt[d];
    int cp = lane & 15;          // channel-pair index
    int hid = lane >> 4;         // 0: even edges, 1: odd edges
    float ax = 0.f, ay = 0.f;
    if (hid == 0) {
        float2 t = __half22float2(from[(size_t)d * 16 + cp]);
        ax = t.x; ay = t.y;
    }
    for (int j0 = 0; j0 < cnt; j0 += 32) {
        int jn = min(32, cnt - j0);
        if (lane < jn) sIdx[lane] = g_esrc[base + j0 + lane];
        __syncwarp();
        int j = 0;
        for (; j + 8 <= jn; j += 8) {
            int s0 = sIdx[j + hid];
            int s1 = sIdx[j + 2 + hid];
            int s2 = sIdx[j + 4 + hid];
            int s3 = sIdx[j + 6 + hid];
            float2 v0 = __half22float2(from[(size_t)s0 * 16 + cp]);
            float2 v1 = __half22float2(from[(size_t)s1 * 16 + cp]);
            float2 v2 = __half22float2(from[(size_t)s2 * 16 + cp]);
            float2 v3 = __half22float2(from[(size_t)s3 * 16 + cp]);
            ax += (v0.x + v1.x) + (v2.x + v3.x);
            ay += (v0.y + v1.y) + (v2.y + v3.y);
        }
        for (; j + 2 <= jn; j += 2) {
            int s = sIdx[j + hid];
            float2 v = __half22float2(from[(size_t)s * 16 + cp]);
            ax += v.x; ay += v.y;
        }
        if (j < jn && hid == 0) {
            int s = sIdx[j];
            float2 v = __half22float2(from[(size_t)s * 16 + cp]);
            ax += v.x; ay += v.y;
        }
        __syncwarp();
    }
    ax += __shfl_down_sync(FULL, ax, 16);
    ay += __shfl_down_sync(FULL, ay, 16);
    float hx = __shfl_sync(FULL, ax, lane >> 1);
    float hy = __shfl_sync(FULL, ay, lane >> 1);
    return (lane & 1) ? hy : hx;
}

// ============ gather1 + fused gemm2: hB = fp16(dinv * (relu(dinv*sum + b1) @ W2)) ============
__global__ void k_gather1(const float* __restrict__ W2, const float* __restrict__ b1, int N) {
    __shared__ float sW[HID * HID];
    __shared__ __align__(16) int sIdxAll[8][32];
    for (int i = threadIdx.x; i < HID * HID; i += blockDim.x) sW[i] = W2[i];
    __syncthreads();

    int lane = threadIdx.x & 31;
    int warp = threadIdx.x >> 5;
    int* sIdx = sIdxAll[warp];
    int gwarp = blockIdx.x * (blockDim.x >> 5) + warp;
    int nw = gridDim.x * (blockDim.x >> 5);
    float bb = b1[lane];

    for (int d = gwarp; d < N; d += nw) {
        float t = gather_row_h(g_hA, d, lane, sIdx);
        float dd = g_dinv[d];
        float h = fmaxf(fmaf(dd, t, bb), 0.0f);
        float o = 0.0f;
        #pragma unroll
        for (int k = 0; k < HID; k++) {
            float hk = __shfl_sync(FULL, h, k);
            o = fmaf(hk, sW[k * HID + lane], o);
        }
        g_hB[(size_t)d * HID + lane] = __float2half(dd * o);
    }
}

// ============ gather2 + fused head + exp-sum: scores + Σexp(score) ============
__global__ void k_gather2(const float* __restrict__ Wh, const float* __restrict__ b2,
                          const float* __restrict__ bh, const float* __restrict__ cash,
                          int N) {
    __shared__ __align__(16) int sIdxAll[8][32];
    __shared__ float sE[8];
    int lane = threadIdx.x & 31;
    int warp = threadIdx.x >> 5;
    int* sIdx = sIdxAll[warp];
    int gwarp = blockIdx.x * (blockDim.x >> 5) + warp;
    int nw = gridDim.x * (blockDim.x >> 5);
    float bb = b2[lane], wh = Wh[lane], bhv = bh[0];

    float esum = 0.0f;
    for (int d = gwarp; d < N; d += nw) {
        float t = gather_row_h(g_hB, d, lane, sIdx);
        float dd = g_dinv[d];
        float v = fmaxf(fmaf(dd, t, bb), 0.0f) * wh;
        #pragma unroll
        for (int o = 16; o > 0; o >>= 1) v += __shfl_xor_sync(FULL, v, o);
        if (lane == 0) {
            float sc = v + bhv;
            g_scores[d + 1] = sc;
            esum += expf(sc);
        }
    }
    if (lane == 0) sE[warp] = esum;
    __syncthreads();
    if (threadIdx.x == 0) {
        float s = sE[0] + sE[1] + sE[2] + sE[3] + sE[4] + sE[5] + sE[6] + sE[7];
        if (blockIdx.x == 0) {              // cash slot
            float c = cash[0];
            g_scores[0] = c;
            s += expf(c);
        }
        atomicAdd(&g_sum_v, s);
    }
}

// ============ norm: out = exp(score)/Σ ; tail-zero g_cnt for the next call ============
__global__ void k_norm(float* __restrict__ out, int M) {
    float inv = 1.0f / g_sum_v;
    int i = blockIdx.x * blockDim.x + threadIdx.x;
    if (i < M) out[i] = expf(g_scores[i]) * inv;
    if (i < M - 1) g_cnt[i] = 0;            // N = M-1; ready for next call
}

// ============ launch ============
extern "C" void kernel_launch(void* const* d_in, const int* in_sizes, int n_in,
                              void* d_out, int out_size) {
    const float* x    = (const float*)d_in[0];
    const int*   ei   = (const int*)d_in[1];     // int32 (JAX x64 disabled)
    const float* W1   = (const float*)d_in[2];
    const float* b1   = (const float*)d_in[3];
    const float* W2   = (const float*)d_in[4];
    const float* b2   = (const float*)d_in[5];
    const float* Wh   = (const float*)d_in[6];
    const float* bh   = (const float*)d_in[7];
    const float* cash = (const float*)d_in[8];
    float* out = (float*)d_out;

    int N = in_sizes[0] / IN_DIM;
    int E = in_sizes[1] / 2;
    const int* src = ei;
    const int* dst = ei + E;
    int M = N + 1;

    // CSR bucket build (g_cnt pre-zeroed by previous call's k_norm / static init)
    bool vec4 = ((E & 3) == 0);
    if (vec4) {
        k_count4<<<(E / 4 + 255) / 256, 256>>>(dst, E);
    } else {
        k_count1<<<(E + 255) / 256, 256>>>(dst, E);
    }
    k_prep<<<(N + 255) / 256, 256>>>(N);
    if (vec4) {
        k_fill4<<<(E / 4 + 255) / 256, 256>>>(src, dst, E);
    } else {
        k_fill1<<<(E + 255) / 256, 256>>>(src, dst, E);
    }

    // dense transform on tensor cores
    k_gemm1<<<(N + TILE - 1) / TILE, 256>>>(x, W1, N);

    // layer 1 propagate + fused gemm2
    k_gather1<<<(N + 7) / 8, 256>>>(W2, b1, N);
    // layer 2 propagate + fused head + exp-sum
    k_gather2<<<(N + 7) / 8, 256>>>(Wh, b2, bh, cash, N);

    // normalize (+ reset g_cnt for next call)
    k_norm<<<(M + 255) / 256, 256>>>(out, M);
}